// round 16
// baseline (speedup 1.0000x reference)
#include <cuda_runtime.h>

#define MAXN 512
#define NSLICE 4
#define SPECIAL_ATOM 8

typedef unsigned long long ull;

__device__ float g_part[MAXN][NSLICE];
__device__ int   g_cnt[MAXN];          // zero-initialized; self-resetting

__device__ __forceinline__ float warp_sum(float v) {
    v += __shfl_down_sync(0xffffffffu, v, 16);
    v += __shfl_down_sync(0xffffffffu, v, 8);
    v += __shfl_down_sync(0xffffffffu, v, 4);
    v += __shfl_down_sync(0xffffffffu, v, 2);
    v += __shfl_down_sync(0xffffffffu, v, 1);
    return v;
}

__device__ __forceinline__ float fast_lg2(float x) {
    float r; asm("lg2.approx.ftz.f32 %0, %1;" : "=f"(r) : "f"(x)); return r;
}
__device__ __forceinline__ float fast_ex2(float x) {
    float r; asm("ex2.approx.ftz.f32 %0, %1;" : "=f"(r) : "f"(x)); return r;
}

__device__ __forceinline__ ull pack2(float lo, float hi) {
    ull r; asm("mov.b64 %0, {%1, %2};" : "=l"(r) : "f"(lo), "f"(hi)); return r;
}
__device__ __forceinline__ ull dup2(float v) {
    ull r; asm("mov.b64 %0, {%1, %1};" : "=l"(r) : "f"(v)); return r;
}
__device__ __forceinline__ void unpack2(ull v, float& lo, float& hi) {
    asm("mov.b64 {%0, %1}, %2;" : "=f"(lo), "=f"(hi) : "l"(v));
}
__device__ __forceinline__ ull fma2(ull a, ull b, ull c) {
    ull d; asm("fma.rn.f32x2 %0, %1, %2, %3;" : "=l"(d) : "l"(a), "l"(b), "l"(c)); return d;
}
__device__ __forceinline__ ull mul2(ull a, ull b) {
    ull d; asm("mul.rn.f32x2 %0, %1, %2;" : "=l"(d) : "l"(a), "l"(b)); return d;
}
__device__ __forceinline__ ull add2(ull a, ull b) {
    ull d; asm("add.rn.f32x2 %0, %1, %2;" : "=l"(d) : "l"(a), "l"(b)); return d;
}

// Each CTA = (atom i, slice sl). Compaction into PACKED pair layout ->
// f32x2 2-row triplet loop (zero per-iteration packing) -> partial;
// last-arriving slice combines deterministically + fused MLP.
__global__ __launch_bounds__(256, 3) void fused_kernel(
    const float* __restrict__ x, int N,
    const float* __restrict__ w1a, const float* __restrict__ b1a,
    const float* __restrict__ w2a, const float* __restrict__ b2a,
    const float* __restrict__ w3a, const float* __restrict__ b3a,
    const float* __restrict__ w1b, const float* __restrict__ b1b,
    const float* __restrict__ w2b, const float* __restrict__ b2b,
    const float* __restrict__ w3b, const float* __restrict__ b3b,
    float* __restrict__ out)
{
    const int i  = blockIdx.x >> 2;        // atom
    const int sl = blockIdx.x & 3;         // slice
    // packed pair layout: pair p holds neighbors (2p, 2p+1)
    //   sKxy[p] = { (ux_e,ux_o), (uy_e,uy_o) }
    //   sKzw[p] = { (uz_e,uz_o), (D_e, D_o) }
    //   sKsl[p] = { (D2_e,D2_o), (lga_e,lga_o) }   lga = lg2(a_ij)
    __shared__ ulonglong2 sKxy[(MAXN + 64) / 2];
    __shared__ ulonglong2 sKzw[(MAXN + 64) / 2];
    __shared__ ulonglong2 sKsl[(MAXN + 64) / 2];
    __shared__ float  sW[1841];
    __shared__ int    cnt[16], off[16];
    __shared__ float  red[8], wr[8];
    __shared__ int    Msh, isLastSh;
    __shared__ float  sRad, sAng, sH1[40], sH2[40];

    const int tid  = threadIdx.x;
    const int lane = tid & 31;
    const int w    = tid >> 5;

    const float xi0 = x[3 * i], xi1 = x[3 * i + 1], xi2 = x[3 * i + 2];
    const float NEGINF = __int_as_float(0xff800000);

    float* fxy = (float*)sKxy;
    float* fzw = (float*)sKzw;
    float* fsl = (float*)sKsl;

    // --- phase 1: 8 warps x 2 passes cover 16 chunks of 32 atoms ---
    bool  ev[2];  int erank[2];
    float eux[2], euy[2], euz[2], eD[2], eD2[2], elg[2];
    float rad = 0.f;
    #pragma unroll
    for (int pass = 0; pass < 2; pass++) {
        const int c = w + 8 * pass;
        const int j = c * 32 + lane;
        float dx = 0.f, dy = 0.f, dz = 0.f, D2 = 1e9f;
        bool valid = false;
        if (j < N) {
            dx = xi0 - x[3 * j];
            dy = xi1 - x[3 * j + 1];
            dz = xi2 - x[3 * j + 2];
            D2 = fmaf(dx, dx, fmaf(dy, dy, dz * dz));
            valid = (j != i) && (D2 <= 36.f);
        }
        unsigned mask = __ballot_sync(0xffffffffu, valid);
        ev[pass] = valid;
        erank[pass] = __popc(mask & ((1u << lane) - 1u));
        if (valid) {
            float inv = rsqrtf(D2);
            float D = D2 * inv;
            float fc = fmaf(0.5f, __cosf(0.5235987755982988f * D), 0.5f);
            float a = __expf(-0.5f * D2) * fc;     // ETA = 0.5
            float dm = D - 1.f;                     // RS = 1
            rad += __expf(-0.5f * dm * dm) * fc;
            eux[pass] = dx * inv; euy[pass] = dy * inv; euz[pass] = dz * inv;
            eD[pass] = D; eD2[pass] = D2;
            elg[pass] = fast_lg2(a);
        }
        if (lane == 0) cnt[c] = __popc(mask);
    }
    rad = warp_sum(rad);
    if (lane == 0) red[w] = rad;
    __syncthreads();

    // --- phase 2: prefix scan + radial total ---
    if (tid < 16) {
        int c = cnt[tid];
        int cs = c;
        #pragma unroll
        for (int d = 1; d < 16; d <<= 1) {
            int t = __shfl_up_sync(0xffffu, cs, d);
            if (tid >= d) cs += t;
        }
        off[tid] = cs - c;
        if (tid == 15) Msh = cs;
        if (tid < 8) {
            float r = red[tid];
            #pragma unroll
            for (int d = 4; d >= 1; d >>= 1) r += __shfl_down_sync(0xffu, r, d);
            if (tid == 0) sRad = r;
        }
    }
    __syncthreads();

    // --- phase 3: scatter into packed layout + sentinels ---
    #pragma unroll
    for (int pass = 0; pass < 2; pass++) {
        if (ev[pass]) {
            int pos = off[w + 8 * pass] + erank[pass];
            int p = pos >> 1, h = pos & 1;
            fxy[4 * p + h]     = eux[pass];
            fxy[4 * p + 2 + h] = euy[pass];
            fzw[4 * p + h]     = euz[pass];
            fzw[4 * p + 2 + h] = eD[pass];
            fsl[4 * p + h]     = eD2[pass];
            fsl[4 * p + 2 + h] = elg[pass];
        }
    }
    const int M = Msh;
    const int Mpad = ((M >> 6) + 1) << 6;      // 64-granular, >= M+1 sentinels
    for (int s = tid; s < Mpad - M; s += 256) {
        int pos = M + s;
        int p = pos >> 1, h = pos & 1;
        fxy[4 * p + h]     = 0.f;
        fxy[4 * p + 2 + h] = 0.f;
        fzw[4 * p + h]     = 0.f;
        fzw[4 * p + 2 + h] = 1e3f;
        fsl[4 * p + h]     = 1e6f;
        fsl[4 * p + 2 + h] = NEGINF;           // lga=-inf -> exact 0
    }
    __syncthreads();

    // packed constants
    const ull K1  = dup2(1.0f);
    const ull K06 = dup2(0.6f);
    const ull KNE = dup2(-0.72134752044448f);
    const ull PC4 = dup2(7.00553e-8f);
    const ull PC3 = dup2(-1.430964e-5f);
    const ull PC2 = dup2(1.565855e-3f);
    const ull PC1 = dup2(-6.8538918e-2f);

    // --- phase 4: 2-row (one pair) blocks, zigzag streams, packed k-pairs ---
    const int strm = 4 * w + sl;               // 0..31
    const int npair = Mpad >> 1;
    float accw = 0.f;
    for (int rnd = 0; 64 * rnd < M; rnd++) {
        const int blk = 32 * rnd + ((rnd & 1) ? (31 - strm) : strm);
        const int j0 = 2 * blk;
        if (j0 >= M) continue;
        const int j1 = j0 + 1;                 // may be sentinel M (lga=-inf -> 0)
        const int p0 = blk;
        // row scalars (halves of pair p0)
        const float ux0 = fxy[4 * p0],     ux1 = fxy[4 * p0 + 1];
        const float uy0 = fxy[4 * p0 + 2], uy1 = fxy[4 * p0 + 3];
        const float uz0 = fzw[4 * p0],     uz1 = fzw[4 * p0 + 1];
        const float D0  = fzw[4 * p0 + 2], D1  = fzw[4 * p0 + 3];
        const float s0  = fsl[4 * p0],     s1  = fsl[4 * p0 + 1];
        const float lg0 = fsl[4 * p0 + 2], lg1 = fsl[4 * p0 + 3];
        // row constants: -0.8 folded into u; q recovered via 2.5*D scale
        const ull X0 = dup2(-0.8f * ux0), Y0 = dup2(-0.8f * uy0), Z0 = dup2(-0.8f * uz0);
        const ull X1 = dup2(-0.8f * ux1), Y1 = dup2(-0.8f * uy1), Z1 = dup2(-0.8f * uz1);
        const ull C0 = dup2(2.5f * D0),   C1 = dup2(2.5f * D1);
        const ull S0 = dup2(s0),          S1 = dup2(s1);
        ull acc0 = 0, acc1 = 0;

        const int pt0 = (j0 & ~63) >> 1;       // first (peel) tile
        {   // peel tile: packed body + 0/1 mask
            const int pp = pt0 + lane;
            ulonglong2 kxy = sKxy[pp], kzw = sKzw[pp], ksl = sKsl[pp];
            const int klo = 2 * pp;
            const ull M0 = pack2(klo > j0 ? 1.f : 0.f, klo + 1 > j0 ? 1.f : 0.f);
            const ull M1 = pack2(klo > j1 ? 1.f : 0.f, klo + 1 > j1 ? 1.f : 0.f);
            float lo, hi;
            // row 0
            ull dot = fma2(X0, kxy.x, fma2(Y0, kxy.y, mul2(Z0, kzw.x)));
            ull t2  = add2(dot, K1);
            ull q2  = fma2(mul2(C0, kzw.y), dot, add2(S0, ksl.x));
            unpack2(t2, lo, hi);
            ull lg  = pack2(fast_lg2(lo), fast_lg2(hi));
            ull z2  = fma2(K06, lg, fma2(KNE, q2, ksl.y));
            unpack2(z2, lo, hi);
            ull P2  = mul2(pack2(fast_ex2(lo), fast_ex2(hi)), M0);
            ull p2  = fma2(PC4, q2, PC3);
            p2 = fma2(p2, q2, PC2); p2 = fma2(p2, q2, PC1); p2 = fma2(p2, q2, K1);
            acc0 = fma2(P2, p2, acc0);
            // row 1
            dot = fma2(X1, kxy.x, fma2(Y1, kxy.y, mul2(Z1, kzw.x)));
            t2  = add2(dot, K1);
            q2  = fma2(mul2(C1, kzw.y), dot, add2(S1, ksl.x));
            unpack2(t2, lo, hi);
            lg  = pack2(fast_lg2(lo), fast_lg2(hi));
            z2  = fma2(K06, lg, fma2(KNE, q2, ksl.y));
            unpack2(z2, lo, hi);
            P2  = mul2(pack2(fast_ex2(lo), fast_ex2(hi)), M1);
            p2  = fma2(PC4, q2, PC3);
            p2 = fma2(p2, q2, PC2); p2 = fma2(p2, q2, PC1); p2 = fma2(p2, q2, K1);
            acc1 = fma2(P2, p2, acc1);
        }
        // clean tiles: pure packed, no masks
        #pragma unroll 2
        for (int pt = pt0 + 32; pt < npair; pt += 32) {
            const int pp = pt + lane;
            ulonglong2 kxy = sKxy[pp], kzw = sKzw[pp], ksl = sKsl[pp];
            float lo, hi;
            ull dot = fma2(X0, kxy.x, fma2(Y0, kxy.y, mul2(Z0, kzw.x)));
            ull t2  = add2(dot, K1);
            ull q2  = fma2(mul2(C0, kzw.y), dot, add2(S0, ksl.x));
            unpack2(t2, lo, hi);
            ull lg  = pack2(fast_lg2(lo), fast_lg2(hi));
            ull z2  = fma2(K06, lg, fma2(KNE, q2, ksl.y));
            unpack2(z2, lo, hi);
            ull P2  = pack2(fast_ex2(lo), fast_ex2(hi));
            ull p2  = fma2(PC4, q2, PC3);
            p2 = fma2(p2, q2, PC2); p2 = fma2(p2, q2, PC1); p2 = fma2(p2, q2, K1);
            acc0 = fma2(P2, p2, acc0);
            dot = fma2(X1, kxy.x, fma2(Y1, kxy.y, mul2(Z1, kzw.x)));
            t2  = add2(dot, K1);
            q2  = fma2(mul2(C1, kzw.y), dot, add2(S1, ksl.x));
            unpack2(t2, lo, hi);
            lg  = pack2(fast_lg2(lo), fast_lg2(hi));
            z2  = fma2(K06, lg, fma2(KNE, q2, ksl.y));
            unpack2(z2, lo, hi);
            P2  = pack2(fast_ex2(lo), fast_ex2(hi));
            p2  = fma2(PC4, q2, PC3);
            p2 = fma2(p2, q2, PC2); p2 = fma2(p2, q2, PC1); p2 = fma2(p2, q2, K1);
            acc1 = fma2(P2, p2, acc1);
        }
        float l0, h0, l1, h1v;
        unpack2(acc0, l0, h0);
        unpack2(acc1, l1, h1v);
        accw = fmaf(fast_ex2(lg0), l0 + h0, accw);   // * a_ij (row 0)
        accw = fmaf(fast_ex2(lg1), l1 + h1v, accw);  // * a_ij (row 1; 0 if sentinel)
    }

    accw = warp_sum(accw);
    if (lane == 0) wr[w] = accw;
    __syncthreads();

    // --- publish slice partial; elect last-arriving CTA of this atom ---
    if (tid == 0) {
        float ssum = 0.f;
        #pragma unroll
        for (int q = 0; q < 8; q++) ssum += wr[q];
        g_part[i][sl] = ssum;
        __threadfence();
        int old = atomicAdd(&g_cnt[i], 1);
        int last = (old == NSLICE - 1);
        isLastSh = last;
        if (last) g_cnt[i] = 0;   // reset for next launch / graph replay
    }
    __syncthreads();
    if (!isLastSh) return;

    // --- last CTA: stage weights, deterministic combine, fused MLP ---
    const bool sp = (i == SPECIAL_ATOM);
    const float* W1 = sp ? w1b : w1a;  const float* B1 = sp ? b1b : b1a;
    const float* W2 = sp ? w2b : w2a;  const float* B2 = sp ? b2b : b2a;
    const float* W3 = sp ? w3b : w3a;  const float* B3 = sp ? b3b : b3a;
    for (int t = tid; t < 1841; t += 256) {
        float v;
        if (t < 80)        v = W1[t];
        else if (t < 120)  v = B1[t - 80];
        else if (t < 1760) { int r = (t - 120) / 41, c = (t - 120) - 41 * r;
                             v = (c < 40) ? W2[r * 40 + c] : 0.f; }
        else if (t < 1800) v = B2[t - 1760];
        else if (t < 1840) v = W3[t - 1800];
        else               v = B3[0];
        sW[t] = v;
    }
    if (tid == 0) {
        float s4 = 0.f;
        #pragma unroll
        for (int q = 0; q < NSLICE; q++) s4 += __ldcg(&g_part[i][q]);  // fixed order
        sAng = 1.3195079107728942f * s4;   // 2^(1-ZETA)
    }
    __syncthreads();

    if (tid < 40) {
        float z = fmaf(sW[2 * tid], sAng, fmaf(sW[2 * tid + 1], sRad, sW[80 + tid]));
        sH1[tid] = __fdividef(1.f, fmaf(z, z, 1.f));
    }
    __syncthreads();
    if (tid < 40) {
        float z = sW[1760 + tid];
        const float* row = sW + 120 + tid * 41;
        #pragma unroll 8
        for (int k = 0; k < 40; k++) z = fmaf(row[k], sH1[k], z);
        sH2[tid] = __fdividef(1.f, fmaf(z, z, 1.f));
    }
    __syncthreads();
    if (w == 0) {
        float v = sW[1800 + lane] * sH2[lane];
        if (lane < 8) v = fmaf(sW[1832 + lane], sH2[32 + lane], v);
        v = warp_sum(v);
        if (lane == 0) out[i] = v + sW[1840];
    }
}

extern "C" void kernel_launch(void* const* d_in, const int* in_sizes, int n_in,
                              void* d_out, int out_size) {
    const float* x = (const float*)d_in[0];
    const int N = in_sizes[0] / 3;

    fused_kernel<<<NSLICE * N, 256>>>(
        x, N,
        (const float*)d_in[1],  (const float*)d_in[2],  (const float*)d_in[3],
        (const float*)d_in[4],  (const float*)d_in[5],  (const float*)d_in[6],
        (const float*)d_in[7],  (const float*)d_in[8],  (const float*)d_in[9],
        (const float*)d_in[10], (const float*)d_in[11], (const float*)d_in[12],
        (float*)d_out);
}

// round 17
// speedup vs baseline: 1.0010x; 1.0010x over previous
#include <cuda_runtime.h>

#define MAXN 512
#define NSLICE 2
#define SPECIAL_ATOM 8

__device__ float g_part[MAXN][NSLICE];
__device__ int   g_cnt[MAXN];          // zero-initialized; self-resetting

__device__ __forceinline__ float warp_sum(float v) {
    v += __shfl_down_sync(0xffffffffu, v, 16);
    v += __shfl_down_sync(0xffffffffu, v, 8);
    v += __shfl_down_sync(0xffffffffu, v, 4);
    v += __shfl_down_sync(0xffffffffu, v, 2);
    v += __shfl_down_sync(0xffffffffu, v, 1);
    return v;
}

__device__ __forceinline__ float fast_lg2(float x) {
    float r; asm("lg2.approx.ftz.f32 %0, %1;" : "=f"(r) : "f"(x)); return r;
}
__device__ __forceinline__ float fast_ex2(float x) {
    float r; asm("ex2.approx.ftz.f32 %0, %1;" : "=f"(r) : "f"(x)); return r;
}

// fc(D)=0.5*(cos(pi*D/6)+1) deg-4 Taylor in s=D^2; error weighted by the
// fused exp(-0.7213*s) factor stays well under 1e-4 everywhere it matters.
__device__ __forceinline__ float fc_poly(float s) {
    float p = 7.00553e-8f;
    p = fmaf(p, s, -1.430964e-5f);
    p = fmaf(p, s, 1.565855e-3f);
    p = fmaf(p, s, -6.8538918e-2f);
    p = fmaf(p, s, 1.0f);
    return p;
}

// Each CTA = (atom i, half sl). Compaction -> scalar 2-row triplet loop with
// lga folded into the EX2 -> partial; last-arriving half combines + MLP.
// launch_bounds(256,5): <=51 regs -> 5 CTAs/SM -> 40 resident warps.
__global__ __launch_bounds__(256, 5) void fused_kernel(
    const float* __restrict__ x, int N,
    const float* __restrict__ w1a, const float* __restrict__ b1a,
    const float* __restrict__ w2a, const float* __restrict__ b2a,
    const float* __restrict__ w3a, const float* __restrict__ b3a,
    const float* __restrict__ w1b, const float* __restrict__ b1b,
    const float* __restrict__ w2b, const float* __restrict__ b2b,
    const float* __restrict__ w3b, const float* __restrict__ b3b,
    float* __restrict__ out)
{
    const int i  = blockIdx.x >> 1;        // atom
    const int sl = blockIdx.x & 1;         // half
    __shared__ float4 sU[MAXN + 32];       // {ux, uy, uz, D}
    __shared__ float2 sB[MAXN + 32];       // {D^2, lg2(a_ij)}
    __shared__ float  sW[1841];
    __shared__ int    cnt[16], off[16];
    __shared__ float  red[8], wr[8];
    __shared__ int    Msh, isLastSh;
    __shared__ float  sRad, sAng, sH1[40], sH2[40];

    const int tid  = threadIdx.x;
    const int lane = tid & 31;
    const int w    = tid >> 5;

    const float xi0 = x[3 * i], xi1 = x[3 * i + 1], xi2 = x[3 * i + 2];
    const float NEGINF = __int_as_float(0xff800000);

    // --- phase 1: 8 warps x 2 passes cover 16 chunks of 32 atoms ---
    bool  ev[2];  int erank[2];
    float eux[2], euy[2], euz[2], eD[2], eD2[2], elg[2];
    float rad = 0.f;
    #pragma unroll
    for (int pass = 0; pass < 2; pass++) {
        const int c = w + 8 * pass;
        const int j = c * 32 + lane;
        float dx = 0.f, dy = 0.f, dz = 0.f, D2 = 1e9f;
        bool valid = false;
        if (j < N) {
            dx = xi0 - x[3 * j];
            dy = xi1 - x[3 * j + 1];
            dz = xi2 - x[3 * j + 2];
            D2 = fmaf(dx, dx, fmaf(dy, dy, dz * dz));
            valid = (j != i) && (D2 <= 36.f);
        }
        unsigned mask = __ballot_sync(0xffffffffu, valid);
        ev[pass] = valid;
        erank[pass] = __popc(mask & ((1u << lane) - 1u));
        if (valid) {
            float inv = rsqrtf(D2);
            float D = D2 * inv;
            float fc = fmaf(0.5f, __cosf(0.5235987755982988f * D), 0.5f);
            float a = __expf(-0.5f * D2) * fc;     // ETA = 0.5
            float dm = D - 1.f;                     // RS = 1
            rad += __expf(-0.5f * dm * dm) * fc;
            eux[pass] = dx * inv; euy[pass] = dy * inv; euz[pass] = dz * inv;
            eD[pass] = D; eD2[pass] = D2;
            elg[pass] = fast_lg2(a);               // -inf when a == 0
        }
        if (lane == 0) cnt[c] = __popc(mask);
    }
    rad = warp_sum(rad);
    if (lane == 0) red[w] = rad;
    __syncthreads();

    // --- phase 2: prefix scan + radial total ---
    if (tid < 16) {
        int c = cnt[tid];
        int cs = c;
        #pragma unroll
        for (int d = 1; d < 16; d <<= 1) {
            int t = __shfl_up_sync(0xffffu, cs, d);
            if (tid >= d) cs += t;
        }
        off[tid] = cs - c;
        if (tid == 15) Msh = cs;
        if (tid < 8) {
            float r = red[tid];
            #pragma unroll
            for (int d = 4; d >= 1; d >>= 1) r += __shfl_down_sync(0xffu, r, d);
            if (tid == 0) sRad = r;
        }
    }
    __syncthreads();

    // --- phase 3: scatter + sentinels ---
    #pragma unroll
    for (int pass = 0; pass < 2; pass++) {
        if (ev[pass]) {
            int pos = off[w + 8 * pass] + erank[pass];
            sU[pos] = make_float4(eux[pass], euy[pass], euz[pass], eD[pass]);
            sB[pos] = make_float2(eD2[pass], elg[pass]);
        }
    }
    const int M = Msh;
    const int Mpad = ((M >> 5) + 1) << 5;      // >= M+1 sentinels
    if (tid < Mpad - M) {
        sU[M + tid] = make_float4(0.f, 0.f, 0.f, 1e3f);
        sB[M + tid] = make_float2(1e6f, NEGINF);  // lga=-inf -> exact 0
    }
    __syncthreads();

    // --- phase 4: scalar 2-row blocks; 16 zigzag streams over both halves ---
    const int strm = w + 8 * sl;               // 0..15
    float accw = 0.f;
    for (int rnd = 0; 32 * rnd < M; rnd++) {
        const int blk = 16 * rnd + ((rnd & 1) ? (15 - strm) : strm);
        const int j0 = 2 * blk;
        if (j0 >= M) continue;
        const int j1 = j0 + 1;                 // index M is the lga=-inf sentinel
        const float4 u0 = sU[j0], u1 = sU[j1];
        const float2 b0 = sB[j0], b1 = sB[j1];
        const float cn0 = -2.f * u0.w, s0 = b0.x;
        const float cn1 = -2.f * u1.w, s1 = b1.x;
        float acc0 = 0.f, acc1 = 0.f;

        const int t0 = j0 & ~31;               // tile containing j0 and j1
        {   // peel tile (predicated)
            const int kk = t0 + lane;
            float4 uk = sU[kk]; float2 bk = sB[kk];
            float d, t, q, P;
            d = fmaf(u0.x, uk.x, fmaf(u0.y, uk.y, u0.z * uk.z));
            t = fmaf(-0.8f, d, 1.0f);
            q = fmaf(cn0 * uk.w, d, s0 + bk.x);
            P = fast_ex2(fmaf(0.6f, fast_lg2(t), fmaf(-0.72134752044448f, q, bk.y)));
            if (kk > j0) acc0 = fmaf(P, fc_poly(q), acc0);
            d = fmaf(u1.x, uk.x, fmaf(u1.y, uk.y, u1.z * uk.z));
            t = fmaf(-0.8f, d, 1.0f);
            q = fmaf(cn1 * uk.w, d, s1 + bk.x);
            P = fast_ex2(fmaf(0.6f, fast_lg2(t), fmaf(-0.72134752044448f, q, bk.y)));
            if (kk > j1) acc1 = fmaf(P, fc_poly(q), acc1);
        }
        // clean tiles
        #pragma unroll 2
        for (int tt = t0 + 32; tt < Mpad; tt += 32) {
            const int kk = tt + lane;
            float4 uk = sU[kk]; float2 bk = sB[kk];
            float d, t, q, P;
            d = fmaf(u0.x, uk.x, fmaf(u0.y, uk.y, u0.z * uk.z));
            t = fmaf(-0.8f, d, 1.0f);
            q = fmaf(cn0 * uk.w, d, s0 + bk.x);
            P = fast_ex2(fmaf(0.6f, fast_lg2(t), fmaf(-0.72134752044448f, q, bk.y)));
            acc0 = fmaf(P, fc_poly(q), acc0);
            d = fmaf(u1.x, uk.x, fmaf(u1.y, uk.y, u1.z * uk.z));
            t = fmaf(-0.8f, d, 1.0f);
            q = fmaf(cn1 * uk.w, d, s1 + bk.x);
            P = fast_ex2(fmaf(0.6f, fast_lg2(t), fmaf(-0.72134752044448f, q, bk.y)));
            acc1 = fmaf(P, fc_poly(q), acc1);
        }
        // row factors a_ij = ex2(lga_j); sentinel row gives exactly 0
        accw = fmaf(fast_ex2(b0.y), acc0, accw);
        accw = fmaf(fast_ex2(b1.y), acc1, accw);
    }

    accw = warp_sum(accw);
    if (lane == 0) wr[w] = accw;
    __syncthreads();

    // --- publish half partial; elect last-arriving CTA of this atom ---
    if (tid == 0) {
        float ssum = 0.f;
        #pragma unroll
        for (int q = 0; q < 8; q++) ssum += wr[q];
        g_part[i][sl] = ssum;
        __threadfence();
        int old = atomicAdd(&g_cnt[i], 1);
        int last = (old == NSLICE - 1);
        isLastSh = last;
        if (last) g_cnt[i] = 0;   // reset for next launch / graph replay
    }
    __syncthreads();
    if (!isLastSh) return;

    // --- last CTA: stage weights, deterministic combine, fused MLP ---
    const bool sp = (i == SPECIAL_ATOM);
    const float* W1 = sp ? w1b : w1a;  const float* B1 = sp ? b1b : b1a;
    const float* W2 = sp ? w2b : w2a;  const float* B2 = sp ? b2b : b2a;
    const float* W3 = sp ? w3b : w3a;  const float* B3 = sp ? b3b : b3a;
    for (int t = tid; t < 1841; t += 256) {
        float v;
        if (t < 80)        v = W1[t];
        else if (t < 120)  v = B1[t - 80];
        else if (t < 1760) { int r = (t - 120) / 41, c = (t - 120) - 41 * r;
                             v = (c < 40) ? W2[r * 40 + c] : 0.f; }
        else if (t < 1800) v = B2[t - 1760];
        else if (t < 1840) v = W3[t - 1800];
        else               v = B3[0];
        sW[t] = v;
    }
    if (tid == 0) {
        float s2 = 0.f;
        #pragma unroll
        for (int q = 0; q < NSLICE; q++) s2 += __ldcg(&g_part[i][q]);  // fixed order
        sAng = 1.3195079107728942f * s2;   // 2^(1-ZETA)
    }
    __syncthreads();

    if (tid < 40) {
        float z = fmaf(sW[2 * tid], sAng, fmaf(sW[2 * tid + 1], sRad, sW[80 + tid]));
        sH1[tid] = __fdividef(1.f, fmaf(z, z, 1.f));
    }
    __syncthreads();
    if (tid < 40) {
        float z = sW[1760 + tid];
        const float* row = sW + 120 + tid * 41;
        #pragma unroll 8
        for (int k = 0; k < 40; k++) z = fmaf(row[k], sH1[k], z);
        sH2[tid] = __fdividef(1.f, fmaf(z, z, 1.f));
    }
    __syncthreads();
    if (w == 0) {
        float v = sW[1800 + lane] * sH2[lane];
        if (lane < 8) v = fmaf(sW[1832 + lane], sH2[32 + lane], v);
        v = warp_sum(v);
        if (lane == 0) out[i] = v + sW[1840];
    }
}

extern "C" void kernel_launch(void* const* d_in, const int* in_sizes, int n_in,
                              void* d_out, int out_size) {
    const float* x = (const float*)d_in[0];
    const int N = in_sizes[0] / 3;

    fused_kernel<<<NSLICE * N, 256>>>(
        x, N,
        (const float*)d_in[1],  (const float*)d_in[2],  (const float*)d_in[3],
        (const float*)d_in[4],  (const float*)d_in[5],  (const float*)d_in[6],
        (const float*)d_in[7],  (const float*)d_in[8],  (const float*)d_in[9],
        (const float*)d_in[10], (const float*)d_in[11], (const float*)d_in[12],
        (float*)d_out);
}